// round 2
// baseline (speedup 1.0000x reference)
#include <cuda_runtime.h>
#include <cstddef>
#include <cstdint>

// Problem shape (fixed by the dataset)
#define NI 16
#define TI 8192
#define DI 512
#define KI 16

#define TT 64          // tokens per tile
#define TPC 2          // tiles per CTA
#define CHUNKS 64      // TI / (TT*TPC)
#define THREADS 256

#define SMEM_FLOATS 42240
#define SMEM_BYTES (SMEM_FLOATS * 4)

// ---------------- device scratch (no allocations allowed) ----------------
__device__ float g_qw[KI * DI];            // query * ln_weight
__device__ float g_c1[KI];                 // sum(q*w) per k
__device__ float g_c2[KI];                 // sum(q*b) per k
__device__ float g_partG[(size_t)NI * CHUNKS * KI * DI]; // per-chunk GEMM2 partials
__device__ float g_partZ[NI * CHUNKS * KI];
__device__ float g_partU[NI * CHUNKS * KI];
__device__ float g_Z[NI * KI];
__device__ float g_U[NI * KI];

// ---------------- prep: qw, c1, c2 ----------------
__global__ void prep_kernel(const float* __restrict__ query,
                            const float* __restrict__ w,
                            const float* __restrict__ b) {
    int tid = threadIdx.x;
    for (int i = tid; i < KI * DI; i += THREADS)
        g_qw[i] = query[i] * w[i & (DI - 1)];
    if (tid < KI) {
        float c1 = 0.f, c2 = 0.f;
        for (int d = 0; d < DI; d++) {
            float q = query[tid * DI + d];
            c1 += q * w[d];
            c2 += q * b[d];
        }
        g_c1[tid] = c1;
        g_c2[tid] = c2;
    }
}

// ---------------- main fused kernel ----------------
// grid: (CHUNKS, NI), 256 threads, dynamic smem
__global__ void __launch_bounds__(THREADS, 1)
main_kernel(const float* __restrict__ tokens,
            const int*   __restrict__ mask,
            float*       __restrict__ attn_out) {
    extern __shared__ float sm[];
    float* tok_s = sm;                     // [64][512] swizzled (f4 slot ^ (tt&7))
    float* qw_s  = sm + TT * DI;           // 32768  [16][512] linear
    float* a_s   = qw_s + KI * DI;         // 40960  [16][64]  e * r
    float* mu_s  = a_s + KI * TT;          // 41984
    float* r_s   = mu_s + TT;              // 42048
    float* z_s   = r_s + TT;               // 42112
    float* u_s   = z_s + KI;               // 42128
    float* c1_s  = u_s + KI;               // 42144
    float* c2_s  = c1_s + KI;              // 42160
    int*   msk_s = (int*)(c2_s + KI);      // 42176 (+64)

    const int tid  = threadIdx.x;
    const int lane = tid & 31;
    const int n     = blockIdx.y;
    const int chunk = blockIdx.x;

    float4* tok4 = (float4*)tok_s;
    float4* qw4  = (float4*)qw_s;

    // load qw (linear layout; GEMM1 reads are warp-broadcast so no swizzle needed)
    {
        const float4* qg = (const float4*)g_qw;
        #pragma unroll
        for (int j = 0; j < (KI * DI / 4) / THREADS; j++) {
            int idx = tid + j * THREADS;
            qw4[idx] = qg[idx];
        }
    }
    if (tid < KI) {
        c1_s[tid] = g_c1[tid];
        c2_s[tid] = g_c2[tid];
        z_s[tid]  = 0.f;
        u_s[tid]  = 0.f;
    }

    // GEMM2 register accumulators: thread owns 4 k x 8 d (as 2 float4)
    const int kg = tid >> 6;   // 0..3
    const int dg = tid & 63;   // f4 slot within row half
    float4 ga[4][2];
    #pragma unroll
    for (int i = 0; i < 4; i++) {
        ga[i][0] = make_float4(0.f, 0.f, 0.f, 0.f);
        ga[i][1] = make_float4(0.f, 0.f, 0.f, 0.f);
    }

    const int tt1 = tid & 63;  // GEMM1 token
    const int kk  = tid >> 6;  // GEMM1 k-group

    for (int tile = 0; tile < TPC; tile++) {
        const int t0 = (chunk * TPC + tile) * TT;
        __syncthreads();  // smem tile reuse barrier

        // ---- load token tile gmem -> smem (swizzled) ----
        {
            const float4* src = (const float4*)(tokens + ((size_t)n * TI + t0) * DI);
            #pragma unroll
            for (int j = 0; j < (TT * DI / 4) / THREADS; j++) {  // 32
                int idx = tid + j * THREADS;
                int tt  = idx >> 7;
                int d4  = idx & 127;
                tok4[tt * 128 + (d4 ^ (tt & 7))] = src[idx];
            }
            if (tid < TT) msk_s[tid] = mask[(size_t)n * TI + t0 + tid];
        }
        __syncthreads();

        // ---- LayerNorm stats: 4 threads per token ----
        // Thread q covers exactly its quarter [q*32, q*32+32) of f4 slots,
        // rotated WITHIN the quarter by lane for bank-conflict freedom.
        // (Per-phase bank groups: (j + 4*(tt&7) + q) mod 8 -> all 8 distinct.)
        {
            int tt = tid >> 2, q = tid & 3;
            float s = 0.f, s2 = 0.f;
            #pragma unroll
            for (int j = 0; j < 32; j++) {
                int slot = q * 32 + ((j + lane) & 31);
                float4 v = tok4[tt * 128 + slot];
                s  += v.x + v.y + v.z + v.w;
                s2 += v.x * v.x + v.y * v.y + v.z * v.z + v.w * v.w;
            }
            s  += __shfl_xor_sync(~0u, s, 1);  s2 += __shfl_xor_sync(~0u, s2, 1);
            s  += __shfl_xor_sync(~0u, s, 2);  s2 += __shfl_xor_sync(~0u, s2, 2);
            if (q == 0) {
                float mu  = s * (1.f / DI);
                float var = s2 * (1.f / DI) - mu * mu;
                mu_s[tt] = mu;
                r_s[tt]  = rsqrtf(var + 1e-5f);
            }
        }
        __syncthreads();

        // ---- GEMM1: raw[k, tt] = qw . tok, thread = (4 k's) x (1 token), full d ----
        float acc[4] = {0.f, 0.f, 0.f, 0.f};
        {
            const float4* trow = tok4 + tt1 * 128;
            const int swt = tt1 & 7;
            const float4* q0 = qw4 + (kk * 4 + 0) * 128;
            const float4* q1 = qw4 + (kk * 4 + 1) * 128;
            const float4* q2 = qw4 + (kk * 4 + 2) * 128;
            const float4* q3 = qw4 + (kk * 4 + 3) * 128;
            #pragma unroll 8
            for (int d4 = 0; d4 < 128; d4++) {
                float4 tv = trow[d4 ^ swt];
                float4 a0 = q0[d4], a1 = q1[d4], a2 = q2[d4], a3 = q3[d4];
                acc[0] += a0.x * tv.x + a0.y * tv.y + a0.z * tv.z + a0.w * tv.w;
                acc[1] += a1.x * tv.x + a1.y * tv.y + a1.z * tv.z + a1.w * tv.w;
                acc[2] += a2.x * tv.x + a2.y * tv.y + a2.z * tv.z + a2.w * tv.w;
                acc[3] += a3.x * tv.x + a3.y * tv.y + a3.z * tv.z + a3.w * tv.w;
            }
        }

        // ---- score -> exp -> attn write + Z/U partial reductions ----
        {
            float mu = mu_s[tt1], r = r_s[tt1];
            int m = msk_s[tt1];
            float e[4], ua[4];
            #pragma unroll
            for (int i = 0; i < 4; i++) {
                int k = kk * 4 + i;
                float sc = r * (acc[i] - mu * c1_s[k]) + c2_s[k];
                float ev = m ? __expf(sc) : 0.f;
                e[i] = ev;
                attn_out[((size_t)(n * KI + k)) * TI + t0 + tt1] = ev; // coalesced
                a_s[k * TT + tt1] = ev * r;
                ua[i] = ev * r * mu;
            }
            #pragma unroll
            for (int i = 0; i < 4; i++) {
                float zz = e[i], uu = ua[i];
                #pragma unroll
                for (int off = 16; off; off >>= 1) {
                    zz += __shfl_xor_sync(~0u, zz, off);
                    uu += __shfl_xor_sync(~0u, uu, off);
                }
                if (lane == 0) {
                    atomicAdd(&z_s[kk * 4 + i], zz);
                    atomicAdd(&u_s[kk * 4 + i], uu);
                }
            }
        }
        __syncthreads();

        // ---- GEMM2: G[k,d] += a[k,tt] * tok[tt,d] ----
        {
            #pragma unroll 4
            for (int tt = 0; tt < TT; tt++) {
                int sl = dg ^ (tt & 7);
                float4 v0 = tok4[tt * 128 + sl];
                float4 v1 = tok4[tt * 128 + sl + 64];   // (dg+64)^sw == (dg^sw)+64
                float a0 = a_s[(kg * 4 + 0) * TT + tt];
                float a1 = a_s[(kg * 4 + 1) * TT + tt];
                float a2 = a_s[(kg * 4 + 2) * TT + tt];
                float a3 = a_s[(kg * 4 + 3) * TT + tt];
                ga[0][0].x += a0 * v0.x; ga[0][0].y += a0 * v0.y; ga[0][0].z += a0 * v0.z; ga[0][0].w += a0 * v0.w;
                ga[0][1].x += a0 * v1.x; ga[0][1].y += a0 * v1.y; ga[0][1].z += a0 * v1.z; ga[0][1].w += a0 * v1.w;
                ga[1][0].x += a1 * v0.x; ga[1][0].y += a1 * v0.y; ga[1][0].z += a1 * v0.z; ga[1][0].w += a1 * v0.w;
                ga[1][1].x += a1 * v1.x; ga[1][1].y += a1 * v1.y; ga[1][1].z += a1 * v1.z; ga[1][1].w += a1 * v1.w;
                ga[2][0].x += a2 * v0.x; ga[2][0].y += a2 * v0.y; ga[2][0].z += a2 * v0.z; ga[2][0].w += a2 * v0.w;
                ga[2][1].x += a2 * v1.x; ga[2][1].y += a2 * v1.y; ga[2][1].z += a2 * v1.z; ga[2][1].w += a2 * v1.w;
                ga[3][0].x += a3 * v0.x; ga[3][0].y += a3 * v0.y; ga[3][0].z += a3 * v0.z; ga[3][0].w += a3 * v0.w;
                ga[3][1].x += a3 * v1.x; ga[3][1].y += a3 * v1.y; ga[3][1].z += a3 * v1.z; ga[3][1].w += a3 * v1.w;
            }
        }
    }

    // ---- flush per-chunk partials (deterministic, no global atomics) ----
    {
        size_t base = ((size_t)n * CHUNKS + chunk) * KI;
        float4* pg = (float4*)g_partG;
        #pragma unroll
        for (int i = 0; i < 4; i++) {
            size_t rb = (base + kg * 4 + i) * (DI / 4);
            pg[rb + dg]      = ga[i][0];
            pg[rb + dg + 64] = ga[i][1];
        }
        if (tid < KI) {
            g_partZ[base + tid] = z_s[tid];
            g_partU[base + tid] = u_s[tid];
        }
    }
}

// ---------------- reduce Z/U over chunks ----------------
__global__ void reduce_zu_kernel() {
    int nk = threadIdx.x;          // 0..255 == n*16 + k
    int nn = nk >> 4, k = nk & 15;
    float z = 0.f, u = 0.f;
    for (int c = 0; c < CHUNKS; c++) {
        int idx = (nn * CHUNKS + c) * KI + k;
        z += g_partZ[idx];
        u += g_partU[idx];
    }
    g_Z[nk] = z;
    g_U[nk] = u;
}

// ---------------- summary finalize ----------------
__global__ void summary_kernel(float* __restrict__ out,
                               const float* __restrict__ w,
                               const float* __restrict__ b) {
    int gid = blockIdx.x * THREADS + threadIdx.x;   // n*K*D layout
    int nn = gid >> 13;            // / (K*D)
    int k  = (gid >> 9) & 15;
    int d  = gid & 511;
    float G = 0.f;
    for (int c = 0; c < CHUNKS; c++)
        G += g_partG[(((size_t)nn * CHUNKS + c) * KI + k) * DI + d];
    float Z = g_Z[nn * KI + k];
    float U = g_U[nn * KI + k];
    out[gid] = (w[d] * (G - U) + b[d] * Z) / Z;
}

// ---------------- attn normalize (in-place on d_out region) ----------------
__global__ void attn_scale_kernel(float* __restrict__ attn) {
    int idx = blockIdx.x * THREADS + threadIdx.x;   // float4 index
    int nk  = idx >> 11;            // / (T/4)
    float s = 1.f / g_Z[nk];
    float4* p = (float4*)attn;
    float4 v = p[idx];
    v.x *= s; v.y *= s; v.z *= s; v.w *= s;
    p[idx] = v;
}

// ---------------- launch ----------------
extern "C" void kernel_launch(void* const* d_in, const int* in_sizes, int n_in,
                              void* d_out, int out_size) {
    const float* tokens = (const float*)d_in[0];
    const int*   mask   = (const int*)d_in[1];
    const float* query  = (const float*)d_in[2];
    const float* w      = (const float*)d_in[3];
    const float* b      = (const float*)d_in[4];
    float* out  = (float*)d_out;
    float* attn = out + NI * KI * DI;   // summary first, then attn

    cudaFuncSetAttribute(main_kernel,
                         cudaFuncAttributeMaxDynamicSharedMemorySize, SMEM_BYTES);

    prep_kernel<<<1, THREADS>>>(query, w, b);
    main_kernel<<<dim3(CHUNKS, NI), THREADS, SMEM_BYTES>>>(tokens, mask, attn);
    reduce_zu_kernel<<<1, THREADS>>>();
    summary_kernel<<<(NI * KI * DI) / THREADS, THREADS>>>(out, w, b);
    attn_scale_kernel<<<(NI * KI * TI / 4) / THREADS, THREADS>>>(attn);
}